// round 10
// baseline (speedup 1.0000x reference)
#include <cuda_runtime.h>

// LIF neuron scan, T=16:
//   u1 = mem*0.5 + x[t]*0.5 ; spike = (u1 > 1) ; mem = spike ? 0 : u1
// HBM-roofline streaming kernel, 512 MB compulsory 1:1 R/W traffic at the
// measured ~6.43 TB/s mixed ceiling (80.4% of 8 TB/s spec).
//
// Operating point, every lever isolated over R1-R9:
//   - 1 float4 column per thread, interleaved t-loop, pointer-bump
//     addressing, exact grid 4096x256, regs 32, occ ~86%  (best profile: R8)
//   - stores: default write-back (.cs stores tested R9: no wall change,
//     worse profile; cross-replay writeback theory disproved)
//   - R10: loads use __ldcg (L2-only) — stream has zero L1 reuse, so skip
//     the L1 fill/tag churn. Unlike .cs (R6 regression) this keeps normal
//     L2 residency.

#define TSTEPS 16

__global__ void __launch_bounds__(256)
lif_scan_kernel(const float* __restrict__ x, float* __restrict__ out)
{
    const unsigned col = blockIdx.x * 256u + threadIdx.x;   // 0 .. 2^20-1
    const unsigned stride4 = 1u << 20;                      // float4 cols per timestep

    const float4* __restrict__ xp = reinterpret_cast<const float4*>(x) + col;
    float4* __restrict__ op = reinterpret_cast<float4*>(out) + col;

    float4 mem = make_float4(0.f, 0.f, 0.f, 0.f);

    #pragma unroll
    for (int t = 0; t < TSTEPS; ++t) {
        const float4 xt = __ldcg(xp);     // L2-only: no L1 fill for read-once stream

        float4 s;
        float u;
        u = fmaf(mem.x, 0.5f, xt.x * 0.5f); s.x = (u > 1.f) ? 1.f : 0.f; mem.x = (u > 1.f) ? 0.f : u;
        u = fmaf(mem.y, 0.5f, xt.y * 0.5f); s.y = (u > 1.f) ? 1.f : 0.f; mem.y = (u > 1.f) ? 0.f : u;
        u = fmaf(mem.z, 0.5f, xt.z * 0.5f); s.z = (u > 1.f) ? 1.f : 0.f; mem.z = (u > 1.f) ? 0.f : u;
        u = fmaf(mem.w, 0.5f, xt.w * 0.5f); s.w = (u > 1.f) ? 1.f : 0.f; mem.w = (u > 1.f) ? 0.f : u;

        *op = s;                          // default write-back (best measured)

        xp += stride4;
        op += stride4;
    }
}

extern "C" void kernel_launch(void* const* d_in, const int* in_sizes, int n_in,
                              void* d_out, int out_size)
{
    const float* x = (const float*)d_in[0];
    float* out = (float*)d_out;

    // 67,108,864 elements / 16 timesteps / 4 per float4 / 256 threads = 4096 CTAs exactly.
    lif_scan_kernel<<<4096, 256>>>(x, out);
}

// round 11
// speedup vs baseline: 1.0194x; 1.0194x over previous
#include <cuda_runtime.h>

// LIF neuron scan, T=16:
//   u1 = mem*0.5 + x[t]*0.5 ; spike = (u1 > 1) ; mem = spike ? 0 : u1
//
// FINAL KERNEL — HBM-roofline streaming. 512 MB compulsory 1:1 R/W traffic
// moved at 6434 GB/s (81.2% DRAM, 80.4% of 8 TB/s spec) = the measured B300
// mixed-stream ceiling. Best isolated profile of the session (ncu 75.4 us, R8).
//
// Every lever isolated over R1-R10:
//   - 1 float4 column per thread, interleaved t-loop (load batching neutral,
//     R2; multi-column + occupancy loss fatal, R3)
//   - plain LDG.128/STG.128: default cache policy beats ALL hint variants
//     (.cs both R2, .cs loads R6, .cs stores R9, .cg loads R10)
//   - regs 32 -> occ ~86%; warp count supplies the MLP
//   - wave-tail quantization irrelevant (R5)
//   - exact grid 4096x256, no guard, 32-bit pointer-bump addressing (R7)

#define TSTEPS 16

__global__ void __launch_bounds__(256)
lif_scan_kernel(const float* __restrict__ x, float* __restrict__ out)
{
    const unsigned col = blockIdx.x * 256u + threadIdx.x;   // 0 .. 2^20-1
    const unsigned stride4 = 1u << 20;                      // float4 cols per timestep

    const float4* __restrict__ xp = reinterpret_cast<const float4*>(x) + col;
    float4* __restrict__ op = reinterpret_cast<float4*>(out) + col;

    float4 mem = make_float4(0.f, 0.f, 0.f, 0.f);

    #pragma unroll
    for (int t = 0; t < TSTEPS; ++t) {
        const float4 xt = *xp;

        float4 s;
        float u;
        u = fmaf(mem.x, 0.5f, xt.x * 0.5f); s.x = (u > 1.f) ? 1.f : 0.f; mem.x = (u > 1.f) ? 0.f : u;
        u = fmaf(mem.y, 0.5f, xt.y * 0.5f); s.y = (u > 1.f) ? 1.f : 0.f; mem.y = (u > 1.f) ? 0.f : u;
        u = fmaf(mem.z, 0.5f, xt.z * 0.5f); s.z = (u > 1.f) ? 1.f : 0.f; mem.z = (u > 1.f) ? 0.f : u;
        u = fmaf(mem.w, 0.5f, xt.w * 0.5f); s.w = (u > 1.f) ? 1.f : 0.f; mem.w = (u > 1.f) ? 0.f : u;

        *op = s;

        xp += stride4;   // single IADD per pointer per step
        op += stride4;
    }
}

extern "C" void kernel_launch(void* const* d_in, const int* in_sizes, int n_in,
                              void* d_out, int out_size)
{
    const float* x = (const float*)d_in[0];
    float* out = (float*)d_out;

    // 67,108,864 elements / 16 timesteps / 4 per float4 / 256 threads = 4096 CTAs exactly.
    lif_scan_kernel<<<4096, 256>>>(x, out);
}

// round 12
// speedup vs baseline: 1.0284x; 1.0088x over previous
#include <cuda_runtime.h>

// LIF neuron scan, T=16:
//   u1 = mem*0.5 + x[t]*0.5 ; spike = (u1 > 1) ; mem = spike ? 0 : u1
//
// HBM-roofline streaming kernel: 512 MB compulsory 1:1 R/W traffic at the
// measured ~6.4 TB/s B300 mixed-stream ceiling (80-81% of 8 TB/s spec).
// Config = R8 optimum (best profile over 11 rounds: 6434 GB/s, DRAM 81.2%,
// ncu 75.4 us), with the final untested knob: block=512 (2048 CTAs).
//
// Lever matrix (all isolated R1-R11):
//   - 1 float4 column/thread, interleaved t-loop (batching neutral R2;
//     multi-column occupancy loss fatal R3)
//   - plain LDG.128/STG.128: default policy beats .cs-both/.cs-ld/.cs-st/
//     .cg-ld (R2/R6/R9/R10)
//   - regs 32, occ ~86%, warp count supplies MLP
//   - block 128 neutral (R5); block 512 tested here
//   - exact grid, no guard, 32-bit pointer-bump addressing (R7)

#define TSTEPS 16

__global__ void __launch_bounds__(512)
lif_scan_kernel(const float* __restrict__ x, float* __restrict__ out)
{
    const unsigned col = blockIdx.x * 512u + threadIdx.x;   // 0 .. 2^20-1
    const unsigned stride4 = 1u << 20;                      // float4 cols per timestep

    const float4* __restrict__ xp = reinterpret_cast<const float4*>(x) + col;
    float4* __restrict__ op = reinterpret_cast<float4*>(out) + col;

    float4 mem = make_float4(0.f, 0.f, 0.f, 0.f);

    #pragma unroll
    for (int t = 0; t < TSTEPS; ++t) {
        const float4 xt = *xp;

        float4 s;
        float u;
        u = fmaf(mem.x, 0.5f, xt.x * 0.5f); s.x = (u > 1.f) ? 1.f : 0.f; mem.x = (u > 1.f) ? 0.f : u;
        u = fmaf(mem.y, 0.5f, xt.y * 0.5f); s.y = (u > 1.f) ? 1.f : 0.f; mem.y = (u > 1.f) ? 0.f : u;
        u = fmaf(mem.z, 0.5f, xt.z * 0.5f); s.z = (u > 1.f) ? 1.f : 0.f; mem.z = (u > 1.f) ? 0.f : u;
        u = fmaf(mem.w, 0.5f, xt.w * 0.5f); s.w = (u > 1.f) ? 1.f : 0.f; mem.w = (u > 1.f) ? 0.f : u;

        *op = s;

        xp += stride4;   // single IADD per pointer per step
        op += stride4;
    }
}

extern "C" void kernel_launch(void* const* d_in, const int* in_sizes, int n_in,
                              void* d_out, int out_size)
{
    const float* x = (const float*)d_in[0];
    float* out = (float*)d_out;

    // 67,108,864 elements / 16 timesteps / 4 per float4 / 512 threads = 2048 CTAs exactly.
    lif_scan_kernel<<<2048, 512>>>(x, out);
}